// round 6
// baseline (speedup 1.0000x reference)
// v5 — single persistent kernel, 148 blocks (1/SM, co-resident), device-wide
// spin barrier between compute phase and sparse-gather phase.
#include <cuda_runtime.h>

#define NN 1024
#define EE 1536
#define MAXDEG 64
#define GRID 148
#define NTH 512

__device__ float g_h[8192 * 64];
__device__ float g_ew[8 * EE];
__device__ int   g_ep0[EE], g_ep1[EE], g_ecnt[EE];   // ecnt zero at load, re-zeroed each run
__device__ int   g_deg[NN];                           // zero at load, re-zeroed each run
__device__ int   g_adj[NN * MAXDEG];
__device__ int   g_bar1, g_bar2;                      // zero at load, re-zeroed each run

__global__ void __launch_bounds__(NTH) mega(
    const float* __restrict__ nodes,   // [8,1024,64] = [8192,64]
    const float* __restrict__ edges,   // [8,1536,32]
    const float* __restrict__ W,       // [64,64]
    const float* __restrict__ evec,    // [32]
    const float* __restrict__ inc,     // [1024,1536]
    const float* __restrict__ lap,     // [1024,1024]
    float* __restrict__ out)           // [8,1024,64]
{
    __shared__ union {
        struct { float XT[64][68]; float Wm[64 * 64]; } g;           // 33.4 KB
        struct { int se[7][MAXDEG]; int so[7][MAXDEG]; float sl[7][MAXDEG];
                 int sdeg[7]; float slii[7]; int smaxd; } q;          // ~5.5 KB
    } sm;

    const int bx  = blockIdx.x;
    const int tid = threadIdx.x;

    // ======================= Phase A =======================
    if (bx < 128) {
        // ---- GEMM role: one 64-row tile of h = X @ W ----
        const int rb = bx * 64;
        for (int t = tid; t < 1024; t += NTH)
            ((float4*)sm.g.Wm)[t] = ((const float4*)W)[t];
        for (int t = tid; t < 1024; t += NTH) {
            float4 v = ((const float4*)nodes)[rb * 16 + t];
            int r = t >> 4, k = (t & 15) << 2;
            sm.g.XT[k + 0][r] = v.x; sm.g.XT[k + 1][r] = v.y;
            sm.g.XT[k + 2][r] = v.z; sm.g.XT[k + 3][r] = v.w;
        }
        __syncthreads();

        const int cg = tid & 31;      // cols 2cg, 2cg+1
        const int rg = tid >> 5;      // rows 4rg .. 4rg+3
        float a00=0,a01=0,a10=0,a11=0,a20=0,a21=0,a30=0,a31=0;
        #pragma unroll 8
        for (int k = 0; k < 64; k++) {
            float4 xv = *(const float4*)&sm.g.XT[k][rg * 4];     // warp broadcast
            float2 wv = *(const float2*)&sm.g.Wm[k * 64 + cg * 2];
            a00 += xv.x * wv.x; a01 += xv.x * wv.y;
            a10 += xv.y * wv.x; a11 += xv.y * wv.y;
            a20 += xv.z * wv.x; a21 += xv.z * wv.y;
            a30 += xv.w * wv.x; a31 += xv.w * wv.y;
        }
        float2* gh2 = (float2*)g_h;
        gh2[(rb + rg * 4 + 0) * 32 + cg] = make_float2(a00, a01);
        gh2[(rb + rg * 4 + 1) * 32 + cg] = make_float2(a10, a11);
        gh2[(rb + rg * 4 + 2) * 32 + cg] = make_float2(a20, a21);
        gh2[(rb + rg * 4 + 3) * 32 + cg] = make_float2(a30, a31);
    } else {
        // ---- extract role (20 blocks): scan inc [1024,1536] as float4 ----
        const int nb = bx - 128;
        const float4* inc4 = (const float4*)inc;
        for (int idx4 = nb * NTH + tid; idx4 < 393216; idx4 += 20 * NTH) {
            float4 v = inc4[idx4];
            int base = idx4 << 2;
            float vals[4] = {v.x, v.y, v.z, v.w};
            #pragma unroll
            for (int c = 0; c < 4; c++) {
                if (vals[c] != 0.f) {
                    int idx = base + c;
                    int i = idx / EE;
                    int e = idx - i * EE;
                    int s = atomicAdd(&g_ecnt[e], 1);
                    if (s == 0) g_ep0[e] = i; else g_ep1[e] = i;
                    int d = atomicAdd(&g_deg[i], 1);
                    if (d < MAXDEG) g_adj[i * MAXDEG + d] = e;
                }
            }
        }
        // ---- ew role: 4 edges per warp-iteration, 8 lanes per edge ----
        const int wg   = nb * 16 + (tid >> 5);   // 0..319
        const int lane = tid & 31;
        const int sub  = lane >> 3;
        const int off  = lane & 7;
        float4 ev = ((const float4*)evec)[off];
        for (int e4 = wg * 4; e4 < 12288; e4 += 320 * 4) {
            int e = e4 + sub;
            float4 d = ((const float4*)edges)[e * 8 + off];
            float s = d.x * ev.x + d.y * ev.y + d.z * ev.z + d.w * ev.w;
            s += __shfl_xor_sync(0xffffffffu, s, 4);
            s += __shfl_xor_sync(0xffffffffu, s, 2);
            s += __shfl_xor_sync(0xffffffffu, s, 1);
            if (off == 0) g_ew[e] = s;
        }
    }

    // ======================= Grid barrier =======================
    __syncthreads();
    if (tid == 0) {
        __threadfence();
        atomicAdd(&g_bar1, 1);
        while (*(volatile int*)&g_bar1 < GRID) __nanosleep(32);
    }
    __syncthreads();

    // ======================= Phase B: gather 7 nodes per block ==========
    // fill metadata for nodes i = bx + 148*t, t = 0..6
    if (tid < 448) {
        const int g    = tid >> 6;
        const int slot = tid & 63;
        const int i    = bx + 148 * g;
        if (i < NN) {
            int d = g_deg[i];
            if (d > MAXDEG) d = MAXDEG;
            if (slot == 0) { sm.q.sdeg[g] = d; sm.q.slii[g] = lap[i * NN + i]; }
            if (slot < d) {
                int e  = g_adj[i * MAXDEG + slot];
                int a0 = g_ep0[e];
                int a1 = g_ep1[e];
                int o  = (a0 == i) ? a1 : a0;
                sm.q.se[g][slot] = e;
                sm.q.so[g][slot] = o;
                sm.q.sl[g][slot] = lap[i * NN + o];
            }
        } else if (slot == 0) {
            sm.q.sdeg[g] = 0; sm.q.slii[g] = 0.f;
        }
    }
    // reset g_ecnt for next run (not read below)
    if (tid >= 32 && tid < 43) {
        int idx = bx + 148 * (tid - 32);
        if (idx < EE) g_ecnt[idx] = 0;
    }
    __syncthreads();
    if (tid == 0) {
        int m = 0;
        #pragma unroll
        for (int t = 0; t < 7; t++) {
            m = max(m, sm.q.sdeg[t]);
            int i = bx + 148 * t;
            if (i < NN) g_deg[i] = 0;            // reset for next run
        }
        sm.q.smaxd = m;
    }
    __syncthreads();

    const int b = tid >> 6;          // batch 0..7
    const int f = tid & 63;          // feature
    const float* hb  = g_h  + b * 65536;
    const float* ewb = g_ew + b * EE;

    int   dloc[7];
    float acc[7], S[7], hv[7];
    #pragma unroll
    for (int t = 0; t < 7; t++) {
        int i = bx + 148 * t;
        dloc[t] = sm.q.sdeg[t];
        acc[t] = 0.f; S[t] = 0.f;
        hv[t] = (i < NN) ? hb[i * 64 + f] : 0.f;
    }
    const int maxd = sm.q.smaxd;
    for (int j = 0; j < maxd; j++) {
        #pragma unroll
        for (int t = 0; t < 7; t++) {
            if (j < dloc[t]) {
                float w = ewb[sm.q.se[t][j]];                    // warp broadcast
                S[t]   += w;
                acc[t] += sm.q.sl[t][j] * w * hb[sm.q.so[t][j] * 64 + f];
            }
        }
    }
    #pragma unroll
    for (int t = 0; t < 7; t++) {
        int i = bx + 148 * t;
        if (i < NN)
            out[(b * NN + i) * 64 + f] = sm.q.slii[t] * S[t] * hv[t] + acc[t];
    }

    // ======================= finish: self-reset barrier state ===========
    __syncthreads();
    if (tid == 0) {
        __threadfence();
        if (atomicAdd(&g_bar2, 1) == GRID - 1) {
            g_bar1 = 0;
            g_bar2 = 0;
        }
    }
}

// ---------------------------------------------------------------------------
extern "C" void kernel_launch(void* const* d_in, const int* in_sizes, int n_in,
                              void* d_out, int out_size)
{
    const float* nodes = (const float*)d_in[0];
    const float* edges = (const float*)d_in[1];
    const float* W     = (const float*)d_in[2];
    const float* evec  = (const float*)d_in[3];
    const float* inc   = (const float*)d_in[4];
    const float* lap   = (const float*)d_in[5];
    float* out = (float*)d_out;

    (void)in_sizes; (void)n_in; (void)out_size;

    mega<<<GRID, NTH>>>(nodes, edges, W, evec, inc, lap, out);
}

// round 7
// speedup vs baseline: 1.8587x; 1.8587x over previous
// v6 — persistent kernel, 148 blocks x 512 thr, extract striped across ALL
// blocks (v5's starvation fix), balanced GEMM blocking, 3-level fill chain.
#include <cuda_runtime.h>

#define NN 1024
#define EE 1536
#define MAXDEG 64
#define GRID 148
#define NTH 512

__device__ float g_h[8192 * 64];
__device__ float g_ew[8 * EE];
__device__ int   g_ep0[EE], g_ep1[EE], g_ecnt[EE];   // ecnt zero at load, re-zeroed each run
__device__ int   g_deg[NN];                           // zero at load, re-zeroed each run
__device__ int   g_adj[NN * MAXDEG];
__device__ int   g_bar1, g_bar2;                      // zero at load, re-zeroed each run

__device__ __forceinline__ void ext_process(float4 v, int idx4)
{
    int base = idx4 << 2;
    float vals[4] = {v.x, v.y, v.z, v.w};
    #pragma unroll
    for (int c = 0; c < 4; c++) {
        if (vals[c] != 0.f) {
            int idx = base + c;
            int i = idx / EE;
            int e = idx - i * EE;
            int s = atomicAdd(&g_ecnt[e], 1);
            if (s == 0) g_ep0[e] = i; else g_ep1[e] = i;
            int d = atomicAdd(&g_deg[i], 1);
            if (d < MAXDEG) g_adj[i * MAXDEG + d] = e;
        }
    }
}

__global__ void __launch_bounds__(NTH) mega(
    const float* __restrict__ nodes,   // [8192,64]
    const float* __restrict__ edges,   // [8,1536,32]
    const float* __restrict__ W,       // [64,64]
    const float* __restrict__ evec,    // [32]
    const float* __restrict__ inc,     // [1024,1536]
    const float* __restrict__ lap,     // [1024,1024]
    float* __restrict__ out)           // [8,1024,64]
{
    __shared__ union {
        struct { float XT[64][68]; float Wm[64 * 64]; } g;            // 33.8 KB
        struct { int se[7][MAXDEG]; int so[7][MAXDEG]; float sl[7][MAXDEG];
                 int sdeg[7]; float slii[7]; int smaxd; } q;
    } sm;

    const int bx  = blockIdx.x;
    const int tid = threadIdx.x;

    // ============ Phase A0: extract, striped across ALL blocks ============
    {
        const float4* inc4 = (const float4*)inc;
        const int base = bx * NTH + tid;                 // < 75776
        float4 v0 = inc4[base + 0 * 75776];
        float4 v1 = inc4[base + 1 * 75776];
        float4 v2 = inc4[base + 2 * 75776];
        float4 v3 = inc4[base + 3 * 75776];
        float4 v4 = inc4[base + 4 * 75776];              // max 378879 < 393216
        ext_process(v0, base);
        ext_process(v1, base + 75776);
        ext_process(v2, base + 151552);
        ext_process(v3, base + 227328);
        ext_process(v4, base + 303104);
        if (base < 14336) {                              // tail: 378880..393215
            float4 v5 = inc4[base + 378880];
            ext_process(v5, base + 378880);
        }
    }

    // ============ Phase A1: role by block ============
    if (bx < 128) {
        // GEMM: 64-row tile, 4x2 micro-tile (LDS/FFMA balanced)
        const int rb = bx * 64;
        for (int t = tid; t < 1024; t += NTH)
            ((float4*)sm.g.Wm)[t] = ((const float4*)W)[t];
        for (int t = tid; t < 1024; t += NTH) {
            float4 v = ((const float4*)nodes)[rb * 16 + t];
            int r = t >> 4, k = (t & 15) << 2;
            sm.g.XT[k + 0][r] = v.x; sm.g.XT[k + 1][r] = v.y;
            sm.g.XT[k + 2][r] = v.z; sm.g.XT[k + 3][r] = v.w;
        }
        __syncthreads();

        const int cg = tid & 31;      // cols 2cg, 2cg+1
        const int rg = tid >> 5;      // rows 4rg..4rg+3  (0..15)
        float a00=0,a01=0,a10=0,a11=0,a20=0,a21=0,a30=0,a31=0;
        #pragma unroll 8
        for (int k = 0; k < 64; k++) {
            float4 xv = *(const float4*)&sm.g.XT[k][rg * 4];   // warp broadcast
            float2 wv = *(const float2*)&sm.g.Wm[k * 64 + cg * 2];
            a00 += xv.x * wv.x; a01 += xv.x * wv.y;
            a10 += xv.y * wv.x; a11 += xv.y * wv.y;
            a20 += xv.z * wv.x; a21 += xv.z * wv.y;
            a30 += xv.w * wv.x; a31 += xv.w * wv.y;
        }
        float2* gh2 = (float2*)g_h;
        gh2[(rb + rg * 4 + 0) * 32 + cg] = make_float2(a00, a01);
        gh2[(rb + rg * 4 + 1) * 32 + cg] = make_float2(a10, a11);
        gh2[(rb + rg * 4 + 2) * 32 + cg] = make_float2(a20, a21);
        gh2[(rb + rg * 4 + 3) * 32 + cg] = make_float2(a30, a31);
    } else {
        // ew role (20 blocks): 4 edges per warp-iter, 8 lanes per edge
        const int wg   = (bx - 128) * 16 + (tid >> 5);   // 0..319
        const int lane = tid & 31;
        const int sub  = lane >> 3;
        const int off  = lane & 7;
        float4 ev = ((const float4*)evec)[off];
        for (int e4 = wg * 4; e4 < 12288; e4 += 320 * 4) {
            int e = e4 + sub;
            float4 d = ((const float4*)edges)[e * 8 + off];
            float s = d.x * ev.x + d.y * ev.y + d.z * ev.z + d.w * ev.w;
            s += __shfl_xor_sync(0xffffffffu, s, 4);
            s += __shfl_xor_sync(0xffffffffu, s, 2);
            s += __shfl_xor_sync(0xffffffffu, s, 1);
            if (off == 0) g_ew[e] = s;
        }
    }

    // ============ Grid barrier ============
    __syncthreads();
    if (tid == 0) {
        __threadfence();
        atomicAdd(&g_bar1, 1);
        while (*(volatile int*)&g_bar1 < GRID) __nanosleep(64);
        __threadfence();
    }
    __syncthreads();

    // ============ Phase B: gather 7 nodes per block ============
    if (tid < 448) {
        const int g    = tid >> 6;
        const int slot = tid & 63;
        const int i    = bx + 148 * g;
        if (i < NN) {
            int d = g_deg[i];                       // issued in parallel
            int e = g_adj[i * MAXDEG + slot];       // with this (no dep; e always a valid id)
            if (d > MAXDEG) d = MAXDEG;
            if (slot == 0) { sm.q.sdeg[g] = d; sm.q.slii[g] = lap[i * NN + i]; }
            int a0 = g_ep0[e];
            int a1 = g_ep1[e];
            int o  = (a0 == i) ? a1 : a0;
            float lv = lap[i * NN + o];
            if (slot < d) {
                sm.q.se[g][slot] = e;
                sm.q.so[g][slot] = o;
                sm.q.sl[g][slot] = lv;
            }
        } else if (slot == 0) {
            sm.q.sdeg[g] = 0; sm.q.slii[g] = 0.f;
        }
    }
    if (tid >= 32 && tid < 43) {                    // reset g_ecnt (not read below)
        int idx = bx + 148 * (tid - 32);
        if (idx < EE) g_ecnt[idx] = 0;
    }
    __syncthreads();
    if (tid == 0) {
        int m = 0;
        #pragma unroll
        for (int t = 0; t < 7; t++) {
            m = max(m, sm.q.sdeg[t]);
            int i = bx + 148 * t;
            if (i < NN) g_deg[i] = 0;               // reset for next run
        }
        sm.q.smaxd = m;
    }
    __syncthreads();

    const int b = tid >> 6;
    const int f = tid & 63;
    const float* hb  = g_h  + b * 65536;
    const float* ewb = g_ew + b * EE;

    int   dloc[7];
    float acc[7], S[7], hv[7];
    #pragma unroll
    for (int t = 0; t < 7; t++) {
        int i = bx + 148 * t;
        dloc[t] = sm.q.sdeg[t];
        acc[t] = 0.f; S[t] = 0.f;
        hv[t] = (i < NN) ? hb[i * 64 + f] : 0.f;
    }
    const int maxd = sm.q.smaxd;
    for (int j = 0; j < maxd; j++) {
        #pragma unroll
        for (int t = 0; t < 7; t++) {
            if (j < dloc[t]) {
                float w = ewb[sm.q.se[t][j]];
                S[t]   += w;
                acc[t] += sm.q.sl[t][j] * w * hb[sm.q.so[t][j] * 64 + f];
            }
        }
    }
    #pragma unroll
    for (int t = 0; t < 7; t++) {
        int i = bx + 148 * t;
        if (i < NN)
            out[(b * NN + i) * 64 + f] = sm.q.slii[t] * S[t] * hv[t] + acc[t];
    }

    // ============ finish: self-reset barrier state ============
    __syncthreads();
    if (tid == 0) {
        __threadfence();
        if (atomicAdd(&g_bar2, 1) == GRID - 1) {
            g_bar1 = 0;
            g_bar2 = 0;
        }
    }
}

// ---------------------------------------------------------------------------
extern "C" void kernel_launch(void* const* d_in, const int* in_sizes, int n_in,
                              void* d_out, int out_size)
{
    const float* nodes = (const float*)d_in[0];
    const float* edges = (const float*)d_in[1];
    const float* W     = (const float*)d_in[2];
    const float* evec  = (const float*)d_in[3];
    const float* inc   = (const float*)d_in[4];
    const float* lap   = (const float*)d_in[5];
    float* out = (float*)d_out;

    (void)in_sizes; (void)n_in; (void)out_size;

    mega<<<GRID, NTH>>>(nodes, edges, W, evec, inc, lap, out);
}